// round 16
// baseline (speedup 1.0000x reference)
#include <cuda_runtime.h>
#include <cuda_fp16.h>
#include <cstdint>

#define N_NODES 50000
#define N_EDGES 1600000
#define BATCH   1024
#define HIDDEN  256
#define NTN     391              // ceil(50000/128)
#define NB1     49               // ceil(50000/1024)
#define NODE_BLKS 12500          // N_NODES/4
#define MSG_BLKS  256            // BATCH/4
#define HIST_BLKS 1563           // ceil(N_EDGES/1024)

// ---------------- scratch (device globals, zero-initialized) ------------------
__device__ __half g_hb [N_NODES*64];    // transformed node features (fp16)
__device__ float g_as4 [N_NODES*4];
__device__ float g_ad4 [N_NODES*4];
__device__ __half g_hB [N_NODES*64];    // h_out (fp16) — B operand
__device__ __half g_m  [BATCH*64];      // msg_emb (fp16) — A operand
__device__ int      g_cnt2[2*N_NODES];  // 2-replica histogram; zeroed by k_agg
__device__ int      g_off [N_NODES];    // partial (per-1024-block) exclusive scan
__device__ uint16_t g_rank[N_EDGES];    // edge rank within its (dst, replica) bucket
__device__ int      g_bsum[64];
__device__ int      g_esrc[N_EDGES];
__device__ float g_pmax[BATCH*NTN];
__device__ float g_psum[BATCH*NTN];
__device__ float g_lse [BATCH];

__device__ __forceinline__ float lrelu(float x) { return fmaxf(x, 0.2f*x); }

// fast exp on FMA/ALU pipes (no MUFU)
__device__ __forceinline__ float fexp(float x) {
  x = fmaxf(fminf(x, 60.0f), -87.0f);
  float y = x * 1.4426950408889634f;
  int   i = __float2int_rn(y);
  float f = y - (float)i;
  float p = 1.33335581e-3f;
  p = p*f + 9.61812911e-3f;
  p = p*f + 5.55041087e-2f;
  p = p*f + 2.40226507e-1f;
  p = p*f + 6.93147180e-1f;
  p = p*f + 1.0f;
  return p * __int_as_float((i + 127) << 23);
}

// exp(x) * 2^-8 (scale folded into exponent bias; x clamped to safe range)
__device__ __forceinline__ float fexp8(float x) {
  x = fmaxf(fminf(x, 60.0f), -60.0f);
  float y = x * 1.4426950408889634f;
  int   i = __float2int_rn(y);
  float f = y - (float)i;
  float p = 1.33335581e-3f;
  p = p*f + 9.61812911e-3f;
  p = p*f + 5.55041087e-2f;
  p = p*f + 2.40226507e-1f;
  p = p*f + 6.93147180e-1f;
  p = p*f + 1.0f;
  return p * __int_as_float((i + 119) << 23);
}

__device__ __forceinline__ uint32_t smem_u32(const void* p) {
  uint32_t a;
  asm("{ .reg .u64 t; cvta.to.shared.u64 t, %1; cvt.u32.u64 %0, t; }" : "=r"(a) : "l"(p));
  return a;
}
__device__ __forceinline__ void ldm_x4(uint32_t& r0, uint32_t& r1, uint32_t& r2,
                                       uint32_t& r3, uint32_t addr) {
  asm volatile("ldmatrix.sync.aligned.m8n8.x4.shared.b16 {%0,%1,%2,%3}, [%4];"
               : "=r"(r0), "=r"(r1), "=r"(r2), "=r"(r3) : "r"(addr));
}
__device__ __forceinline__ void mma16816(float* c, uint32_t a0, uint32_t a1,
                                         uint32_t a2, uint32_t a3,
                                         uint32_t b0, uint32_t b1) {
  asm volatile(
      "mma.sync.aligned.m16n8k16.row.col.f32.f16.f16.f32 "
      "{%0,%1,%2,%3}, {%4,%5,%6,%7}, {%8,%9}, {%0,%1,%2,%3};"
      : "+f"(c[0]), "+f"(c[1]), "+f"(c[2]), "+f"(c[3])
      : "r"(a0), "r"(a1), "r"(a2), "r"(a3), "r"(b0), "r"(b1));
}

__device__ __forceinline__ int wscan(int v, int lane) {
  #pragma unroll
  for (int off = 1; off < 32; off <<= 1) {
    int t = __shfl_up_sync(0xffffffffu, v, off);
    if (lane >= off) v += t;
  }
  return v;
}

// dual warp-scan of the 49 block sums into sOff[64] (call with full block)
__device__ __forceinline__ void scan_bsums(int* sOff) {
  int tid = threadIdx.x;
  if (tid < 32) {
    int lane = tid;
    int a0 = (lane      < NB1) ? g_bsum[lane]      : 0;
    int a1 = (32 + lane < NB1) ? g_bsum[32 + lane] : 0;
    int i0 = wscan(a0, lane);
    int t0 = __shfl_sync(0xffffffffu, i0, 31);
    int i1 = wscan(a1, lane) + t0;
    sOff[lane]      = i0 - a0;
    sOff[32 + lane] = i1 - a1;
  }
  __syncthreads();
}

// ---------------- fused front: node transform | msg_emb | hist+rank -----------
__global__ __launch_bounds__(256) void k_front(
    const float* __restrict__ x, const float* __restrict__ gw,
    const float* __restrict__ aw_s, const float* __restrict__ aw_d,
    const float* __restrict__ msg, const float* __restrict__ fw,
    const float* __restrict__ fb, const int* __restrict__ ei) {
  int bid = blockIdx.x;
  int tid = threadIdx.x;
  if (bid < NODE_BLKS) {
    __shared__ float sw[256];
    __shared__ float satt[128];
    __shared__ float sx[16];
    sw[tid] = gw[tid];
    if (tid < 64)       satt[tid] = aw_s[tid];
    else if (tid < 128) satt[tid] = aw_d[tid-64];
    int n0 = bid*4;
    if (tid < 16) sx[tid] = x[n0*4 + tid];
    __syncthreads();
    int local = tid >> 6, j = tid & 63;
    int node = n0 + local;
    float h = sx[local*4+0]*sw[j]     + sx[local*4+1]*sw[64+j]
            + sx[local*4+2]*sw[128+j] + sx[local*4+3]*sw[192+j];
    g_hb[node*64 + j] = __float2half(h);
    float ps = h*satt[j], pd = h*satt[64+j];
    #pragma unroll
    for (int off = 8; off > 0; off >>= 1) {
      ps += __shfl_xor_sync(0xffffffffu, ps, off);
      pd += __shfl_xor_sync(0xffffffffu, pd, off);
    }
    if ((j & 15) == 0) {
      int head = j >> 4;
      g_as4[node*4+head] = ps;
      g_ad4[node*4+head] = pd;
    }
  } else if (bid < NODE_BLKS + MSG_BLKS) {
    int b = (bid - NODE_BLKS)*4 + (tid >> 6);
    int j = tid & 63;
    const float* mr = msg + b*HIDDEN;
    float acc = fb[j];
    #pragma unroll 8
    for (int k = 0; k < HIDDEN; k++)
      acc += mr[k] * fw[k*64 + j];
    g_m[b*64 + j] = __float2half(acc);
  } else {
    // 2-replica histogram + rank capture; replica = (i>>2)&1 (reproducible)
    int i = (bid - NODE_BLKS - MSG_BLKS)*1024 + tid*4;
    if (i + 4 <= N_EDGES) {
      int rep = (i >> 2) & 1;
      int* cnt = g_cnt2 + rep*N_NODES;
      int4 d4 = *(const int4*)(ei + N_EDGES + i);
      ushort4 r4;
      r4.x = (uint16_t)atomicAdd(&cnt[d4.x], 1);
      r4.y = (uint16_t)atomicAdd(&cnt[d4.y], 1);
      r4.z = (uint16_t)atomicAdd(&cnt[d4.z], 1);
      r4.w = (uint16_t)atomicAdd(&cnt[d4.w], 1);
      *(ushort4*)(g_rank + i) = r4;
    } else {
      for (int e = i; e < N_EDGES; e++) {
        int rep = (e >> 2) & 1;
        g_rank[e] = (uint16_t)atomicAdd(&g_cnt2[rep*N_NODES + ei[N_EDGES + e]], 1);
      }
    }
  }
}

// ---------------- CSR scan over total counts (c0+c1); counters kept for scatter
__global__ void k_scan1() {
  __shared__ int wsum[32];
  int tid = threadIdx.x, lane = tid & 31, wid = tid >> 5;
  int i = blockIdx.x*1024 + tid;
  int v = 0;
  if (i < N_NODES) v = g_cnt2[i] + g_cnt2[N_NODES + i];
  int incl = wscan(v, lane);
  if (lane == 31) wsum[wid] = incl;
  __syncthreads();
  if (wid == 0) wsum[lane] = wscan(wsum[lane], lane);
  __syncthreads();
  int base = wid ? wsum[wid-1] : 0;
  if (i < N_NODES) g_off[i] = base + incl - v;
  if (tid == 1023) g_bsum[blockIdx.x] = wsum[31];
}

// atomic-free scatter: pos = off[d] + sOff[d>>10] + (rep ? c0[d] : 0) + rank
__global__ __launch_bounds__(256) void k_scatter(const int* __restrict__ ei) {
  __shared__ int sOff[64];
  scan_bsums(sOff);
  int i = (blockIdx.x*blockDim.x + threadIdx.x)*4;
  if (i + 4 <= N_EDGES) {
    int rep = (i >> 2) & 1;
    int4 s4 = *(const int4*)(ei + i);
    int4 d4 = *(const int4*)(ei + N_EDGES + i);
    ushort4 r4 = *(const ushort4*)(g_rank + i);
    int b0 = rep ? __ldg(&g_cnt2[d4.x]) : 0;
    int b1 = rep ? __ldg(&g_cnt2[d4.y]) : 0;
    int b2 = rep ? __ldg(&g_cnt2[d4.z]) : 0;
    int b3 = rep ? __ldg(&g_cnt2[d4.w]) : 0;
    int p0 = __ldg(&g_off[d4.x]) + sOff[d4.x >> 10] + b0 + r4.x;
    int p1 = __ldg(&g_off[d4.y]) + sOff[d4.y >> 10] + b1 + r4.y;
    int p2 = __ldg(&g_off[d4.z]) + sOff[d4.z >> 10] + b2 + r4.z;
    int p3 = __ldg(&g_off[d4.w]) + sOff[d4.w >> 10] + b3 + r4.w;
    g_esrc[p0] = s4.x;
    g_esrc[p1] = s4.y;
    g_esrc[p2] = s4.z;
    g_esrc[p3] = s4.w;
  } else {
    for (int e = i; e < N_EDGES; e++) {
      int rep = (e >> 2) & 1;
      int d = ei[N_EDGES + e];
      int pos = g_off[d] + sOff[d >> 10] + (rep ? g_cnt2[d] : 0) + g_rank[e];
      g_esrc[pos] = ei[e];
    }
  }
}

// ---------------- fused softmax + aggregation (one warp / node) ----------------
// Software-pipelined chunks: prefetch next chunk's esrc + as4 gather into
// registers while the HFMA2 inner loop consumes the current chunk.
__global__ __launch_bounds__(256) void k_agg(const float* __restrict__ gat_b) {
  __shared__ int sOff[64];
  __shared__ __align__(16) int     sS [8][32];      // src*32
  __shared__ __align__(16) __half2 sWT[8][4][32];   // [warp][head][edge] (w,w) fp16x2
  scan_bsums(sOff);
  int tid = threadIdx.x;
  int w = tid >> 5, lane = tid & 31;
  int n = (blockIdx.x*blockDim.x + tid) >> 5;   // grid sized exactly: n < N_NODES
  int beg = g_off[n] + sOff[n >> 10];
  int end = (n+1 < N_NODES) ? (__ldg(&g_off[n+1]) + sOff[(n+1) >> 10]) : N_EDGES;
  if (lane == 0) { g_cnt2[n] = 0; g_cnt2[N_NODES + n] = 0; }
  float4 ad = *(const float4*)&g_ad4[n*4];

  int h = lane >> 3;          // head of columns (2l, 2l+1)
  const __half2* hb2 = (const __half2*)g_hb;
  float acc0 = 0.f, acc1 = 0.f;
  float t0 = 0.f, t1 = 0.f, t2 = 0.f, t3 = 0.f;

  // prefetch first chunk
  bool vN = (beg + lane) < end;
  int srcN = 0;
  float4 asN = make_float4(0.f,0.f,0.f,0.f);
  if (vN) {
    srcN = __ldg(&g_esrc[beg + lane]);
    asN  = *(const float4*)&g_as4[srcN*4];
  }

  for (int base = beg; base < end; base += 32) {
    int   src = srcN;
    float4 as = asN;
    bool  v   = vN;
    // prefetch next chunk (overlaps with inner loop below)
    int nb = base + 32;
    vN = (nb + lane) < end;
    if (vN) {
      srcN = __ldg(&g_esrc[nb + lane]);
      asN  = *(const float4*)&g_as4[srcN*4];
    }
    __half2 w0 = __float2half2_rn(0.f), w1 = w0, w2 = w0, w3 = w0;
    if (v) {
      float e0 = fexp8(lrelu(as.x+ad.x));
      float e1 = fexp8(lrelu(as.y+ad.y));
      float e2 = fexp8(lrelu(as.z+ad.z));
      float e3 = fexp8(lrelu(as.w+ad.w));
      t0 += e0; t1 += e1; t2 += e2; t3 += e3;
      w0 = __float2half2_rn(e0);
      w1 = __float2half2_rn(e1);
      w2 = __float2half2_rn(e2);
      w3 = __float2half2_rn(e3);
    }
    sS[w][lane] = (v ? src : 0)*32;
    sWT[w][0][lane] = w0;
    sWT[w][1][lane] = w1;
    sWT[w][2][lane] = w2;
    sWT[w][3][lane] = w3;
    __syncwarp();
    int cnt = min(32, end - base);
    __half2 ah = __float2half2_rn(0.f);
    int j = 0;
    for (; j + 4 <= cnt; j += 4) {
      int4 ss = *(const int4*)&sS[w][j];
      uint2 wp0 = *(const uint2*)&sWT[w][h][j];       // 2 x half2
      uint2 wp1 = *(const uint2*)&sWT[w][h][j+2];
      __half2 v0 = __ldg(&hb2[ss.x + lane]);
      __half2 v1 = __ldg(&hb2[ss.y + lane]);
      __half2 v2 = __ldg(&hb2[ss.z + lane]);
      __half2 v3 = __ldg(&hb2[ss.w + lane]);
      ah = __hfma2(*reinterpret_cast<__half2*>(&wp0.x), v0, ah);
      ah = __hfma2(*reinterpret_cast<__half2*>(&wp0.y), v1, ah);
      ah = __hfma2(*reinterpret_cast<__half2*>(&wp1.x), v2, ah);
      ah = __hfma2(*reinterpret_cast<__half2*>(&wp1.y), v3, ah);
    }
    for (; j < cnt; j++) {
      ah = __hfma2(sWT[w][h][j], __ldg(&hb2[sS[w][j] + lane]), ah);
    }
    float2 af = __half22float2(ah);
    acc0 += af.x;
    acc1 += af.y;
    __syncwarp();
  }
  #pragma unroll
  for (int off = 16; off > 0; off >>= 1) {
    t0 += __shfl_xor_sync(0xffffffffu, t0, off);
    t1 += __shfl_xor_sync(0xffffffffu, t1, off);
    t2 += __shfl_xor_sync(0xffffffffu, t2, off);
    t3 += __shfl_xor_sync(0xffffffffu, t3, off);
  }
  float th = (h == 0) ? t0 : (h == 1) ? t1 : (h == 2) ? t2 : t3;
  float inv = 1.f/(th + 1e-16f);
  float2 gb = *(const float2*)&gat_b[2*lane];
  float v0 = acc0*inv + gb.x;
  float v1 = acc1*inv + gb.y;
  __half2 o2 = __floats2half2_rn(v0, v1);
  ((uint32_t*)g_hB)[n*32 + lane] = *reinterpret_cast<uint32_t*>(&o2);
}

// ---------------- shared GEMM mainloop: fp16 single-term, K=64 (4 ksteps) -----
#define A_LD     144
#define B_LD     144
#define B_OFF    (128*A_LD)                 // 18432
#define SMEM_DYN (128*A_LD + 128*B_LD)      // 36864
#define SLSE_OFF 34304                      // lse cache in gemm2 epilogue
__device__ __forceinline__ void gemm_mainloop(char* smem, uint32_t sb,
                                              int bm, int bn, float acc[4][4][4]) {
  uint32_t sbA = sb;
  uint32_t sbB = sb + B_OFF;
  int tid = threadIdx.x, wid = tid >> 5, lid = tid & 31;

  const uint4* srcA = (const uint4*)g_m;
  const uint4* srcB = (const uint4*)g_hB;
  #pragma unroll
  for (int i = tid; i < 1024; i += 256) {   // A: 128 rows x 8 chunks
    int row = i >> 3, ch = i & 7;
    uint4 va = srcA[(size_t)(bm + row)*8 + ch];
    *(uint4*)(smem + row*A_LD + ch*16) = va;
  }
  #pragma unroll
  for (int i = tid; i < 1024; i += 256) {   // B: 128 rows x 8 chunks
    int row = i >> 3, ch = i & 7;
    int node = bn + row;
    uint4 vb = make_uint4(0u,0u,0u,0u);
    if (node < N_NODES) vb = srcB[(size_t)node*8 + ch];
    *(uint4*)(smem + B_OFF + row*B_LD + ch*16) = vb;
  }
  __syncthreads();

  int wm = wid & 1, wn = wid >> 1;
  #pragma unroll
  for (int i = 0; i < 4; i++)
    #pragma unroll
    for (int j = 0; j < 4; j++)
      #pragma unroll
      for (int c = 0; c < 4; c++) acc[i][j][c] = 0.f;

  #pragma unroll
  for (int ks = 0; ks < 4; ks++) {
    uint32_t a[4][4];
    #pragma unroll
    for (int mf = 0; mf < 4; mf++) {
      uint32_t addr = sbA + (wm*64 + mf*16 + (lid & 15))*A_LD
                          + ks*32 + (lid >> 4)*16;
      ldm_x4(a[mf][0], a[mf][1], a[mf][2], a[mf][3], addr);
    }
    uint32_t b[4][2];
    #pragma unroll
    for (int nfp = 0; nfp < 2; nfp++) {
      uint32_t addr = sbB + (wn*32 + nfp*16 + ((lid >> 4) & 1)*8 + (lid & 7))*B_LD
                          + ks*32 + ((lid >> 3) & 1)*16;
      uint32_t r0, r1, r2, r3;
      ldm_x4(r0, r1, r2, r3, addr);
      b[nfp*2][0] = r0;   b[nfp*2][1] = r1;
      b[nfp*2+1][0] = r2; b[nfp*2+1][1] = r3;
    }
    #pragma unroll
    for (int mf = 0; mf < 4; mf++)
      #pragma unroll
      for (int nf = 0; nf < 4; nf++)
        mma16816(acc[mf][nf], a[mf][0], a[mf][1], a[mf][2], a[mf][3],
                 b[nf][0], b[nf][1]);
  }
}

// ---------------- GEMM pass 1: per-row (max, sumexp) partials only ------------
__global__ __launch_bounds__(256, 2)
void k_gemm1() {
  extern __shared__ char smem[];
  uint32_t sb = smem_u32(smem);
  int tid = threadIdx.x, wid = tid >> 5, lid = tid & 31;
  int bm = blockIdx.x * 128;
  int bn = blockIdx.y * 128;
  bool fullTile = (bn + 128 <= N_NODES);

  float acc[4][4][4];
  gemm_mainloop(smem, sb, bm, bn, acc);
  __syncthreads();

  float* srm = (float*)smem;           // [128][4]
  float* srs = (float*)smem + 512;     // [128][4]
  int wm = wid & 1, wn = wid >> 1;

  #pragma unroll
  for (int mf = 0; mf < 4; mf++) {
    #pragma unroll
    for (int h = 0; h < 2; h++) {
      float v[8];
      #pragma unroll
      for (int nf = 0; nf < 4; nf++) {
        v[nf*2]   = acc[mf][nf][h*2];
        v[nf*2+1] = acc[mf][nf][h*2+1];
      }
      if (!fullTile) {
        #pragma unroll
        for (int nf = 0; nf < 4; nf++) {
          int colb = bn + wn*32 + nf*8 + (lid & 3)*2;
          if (colb   >= N_NODES) v[nf*2]   = -1e30f;
          if (colb+1 >= N_NODES) v[nf*2+1] = -1e30f;
        }
      }
      float m = v[0];
      #pragma unroll
      for (int t = 1; t < 8; t++) m = fmaxf(m, v[t]);
      m = fmaxf(m, __shfl_xor_sync(0xffffffffu, m, 1));
      m = fmaxf(m, __shfl_xor_sync(0xffffffffu, m, 2));
      float s = 0.f;
      #pragma unroll
      for (int t = 0; t < 8; t++) s += fexp(v[t] - m);
      s += __shfl_xor_sync(0xffffffffu, s, 1);
      s += __shfl_xor_sync(0xffffffffu, s, 2);
      if ((lid & 3) == 0) {
        int row = wm*64 + mf*16 + h*8 + (lid >> 2);
        srm[row*4 + wn] = m;
        srs[row*4 + wn] = s;
      }
    }
  }
  __syncthreads();
  if (tid < 128) {
    float m = srm[tid*4];
    m = fmaxf(m, srm[tid*4+1]);
    m = fmaxf(m, srm[tid*4+2]);
    m = fmaxf(m, srm[tid*4+3]);
    float s = 0.f;
    #pragma unroll
    for (int g = 0; g < 4; g++)
      s += srs[tid*4+g] * fexp(srm[tid*4+g] - m);
    g_pmax[(size_t)(bm+tid)*NTN + blockIdx.y] = m;
    g_psum[(size_t)(bm+tid)*NTN + blockIdx.y] = s;
  }
}

// ---------------- final lse from partials --------------------------------------
__global__ void k_lse() {   // grid 128, block 256 (8 warps) -> 1024 rows
  int wid = threadIdx.x >> 5, lid = threadIdx.x & 31;
  int row = blockIdx.x*8 + wid;
  float m = -1e30f, s = 0.f;
  for (int i = lid; i < NTN; i += 32) {
    float mi = g_pmax[(size_t)row*NTN + i];
    float si = g_psum[(size_t)row*NTN + i];
    float nm = fmaxf(m, mi);
    s = s*__expf(m - nm) + si*__expf(mi - nm);
    m = nm;
  }
  #pragma unroll
  for (int off = 16; off > 0; off >>= 1) {
    float om = __shfl_xor_sync(0xffffffffu, m, off);
    float os = __shfl_xor_sync(0xffffffffu, s, off);
    float nm = fmaxf(m, om);
    s = s*__expf(m - nm) + os*__expf(om - nm);
    m = nm;
  }
  if (lid == 0) g_lse[row] = m + logf(s);
}

// ---------------- GEMM pass 2: recompute, subtract lse, coalesced stores ------
// Epilogue stages each 64-row half-tile through smem (reusing the tile region)
// for fully-coalesced float4 stores.
__global__ __launch_bounds__(256, 2)
void k_gemm2(float* __restrict__ out) {
  extern __shared__ char smem[];
  uint32_t sb = smem_u32(smem);
  int tid = threadIdx.x, wid = tid >> 5, lid = tid & 31;
  int bm = blockIdx.x * 128;
  int bn = blockIdx.y * 128;
  bool fullTile = (bn + 128 <= N_NODES);

  float acc[4][4][4];
  gemm_mainloop(smem, sb, bm, bn, acc);
  __syncthreads();

  float* epi  = (float*)smem;                 // [64][132] staging (33792 B)
  float* slse = (float*)(smem + SLSE_OFF);    // [128]
  if (tid < 128) slse[tid] = g_lse[bm + tid];
  __syncthreads();

  int wm = wid & 1, wn = wid >> 1;
  int rsub = (lid >> 2);
  int c0 = (lid & 3)*2;

  #pragma unroll
  for (int half = 0; half < 2; half++) {
    if (wm == half) {
      #pragma unroll
      for (int mf = 0; mf < 4; mf++) {
        int lr = mf*16 + rsub;                 // local row in [0,64)
        #pragma unroll
        for (int nf = 0; nf < 4; nf++) {
          int scol = wn*32 + nf*8 + c0;
          *(float2*)&epi[(lr    )*132 + scol] = make_float2(acc[mf][nf][0], acc[mf][nf][1]);
          *(float2*)&epi[(lr + 8)*132 + scol] = make_float2(acc[mf][nf][2], acc[mf][nf][3]);
        }
      }
    }
    __syncthreads();
    // coalesced store: 64 rows x 128 cols, 8 float4 per thread
    #pragma unroll
    for (int i = tid; i < 64*32; i += 256) {
      int row = i >> 5;
      int cq  = i & 31;
      int col = bn + cq*4;
      if (fullTile || col < N_NODES) {        // N_NODES%4==0 -> all-or-nothing
        float l = slse[half*64 + row];
        float4 v = *(float4*)&epi[row*132 + cq*4];
        v.x -= l; v.y -= l; v.z -= l; v.w -= l;
        *(float4*)(out + (size_t)(bm + half*64 + row)*N_NODES + col) = v;
      }
    }
    __syncthreads();
  }
}

// ---------------- launch --------------------------------------------------------
extern "C" void kernel_launch(void* const* d_in, const int* in_sizes, int n_in,
                              void* d_out, int out_size) {
  const float* message = (const float*)d_in[0];
  const float* x       = (const float*)d_in[1];
  const int*   eidx    = (const int*)  d_in[2];
  const float* gat_w   = (const float*)d_in[3];
  const float* att_src = (const float*)d_in[4];
  const float* att_dst = (const float*)d_in[5];
  const float* gat_b   = (const float*)d_in[6];
  const float* fc_w    = (const float*)d_in[7];
  const float* fc_b    = (const float*)d_in[8];
  float* out = (float*)d_out;

  cudaFuncSetAttribute(k_gemm1, cudaFuncAttributeMaxDynamicSharedMemorySize, SMEM_DYN);
  cudaFuncSetAttribute(k_gemm2, cudaFuncAttributeMaxDynamicSharedMemorySize, SMEM_DYN);

  k_front  <<<NODE_BLKS + MSG_BLKS + HIST_BLKS, 256>>>(
      x, gat_w, att_src, att_dst, message, fc_w, fc_b, eidx);
  k_scan1  <<<NB1, 1024>>>();
  k_scatter<<<HIST_BLKS, 256>>>(eidx);
  k_agg    <<<(N_NODES*32)/256, 256>>>(gat_b);
  k_gemm1  <<<dim3(BATCH/128, NTN), 256, SMEM_DYN>>>();
  k_lse    <<<BATCH/8, 256>>>();
  k_gemm2  <<<dim3(BATCH/128, NTN), 256, SMEM_DYN>>>(out);
}

// round 17
// speedup vs baseline: 1.0496x; 1.0496x over previous
#include <cuda_runtime.h>
#include <cuda_fp16.h>
#include <cstdint>

#define N_NODES 50000
#define N_EDGES 1600000
#define BATCH   1024
#define HIDDEN  256
#define NTN     391              // ceil(50000/128)
#define NB1     49               // ceil(50000/1024)
#define NODE_BLKS 12500          // N_NODES/4
#define MSG_BLKS  256            // BATCH/4
#define HIST_BLKS 1563           // ceil(N_EDGES/1024)

// ---------------- scratch (device globals, zero-initialized) ------------------
__device__ __half g_hb [N_NODES*64];    // transformed node features (fp16)
__device__ float g_as4 [N_NODES*4];
__device__ float g_ad4 [N_NODES*4];
__device__ __half g_hB [N_NODES*64];    // h_out (fp16) — B operand
__device__ __half g_m  [BATCH*64];      // msg_emb (fp16) — A operand
__device__ int      g_cnt2[2*N_NODES];  // 2-replica histogram; zeroed by k_agg
__device__ int      g_off [N_NODES];    // partial (per-1024-block) exclusive scan
__device__ uint16_t g_rank[N_EDGES];    // edge rank within its (dst, replica) bucket
__device__ int      g_bsum[64];
__device__ int      g_esrc[N_EDGES];
__device__ float g_pmax[BATCH*NTN];
__device__ float g_psum[BATCH*NTN];
__device__ float g_lse [BATCH];

__device__ __forceinline__ float lrelu(float x) { return fmaxf(x, 0.2f*x); }

// fast exp on FMA/ALU pipes (no MUFU)
__device__ __forceinline__ float fexp(float x) {
  x = fmaxf(fminf(x, 60.0f), -87.0f);
  float y = x * 1.4426950408889634f;
  int   i = __float2int_rn(y);
  float f = y - (float)i;
  float p = 1.33335581e-3f;
  p = p*f + 9.61812911e-3f;
  p = p*f + 5.55041087e-2f;
  p = p*f + 2.40226507e-1f;
  p = p*f + 6.93147180e-1f;
  p = p*f + 1.0f;
  return p * __int_as_float((i + 127) << 23);
}

// exp(x) * 2^-8 (scale folded into exponent bias; x clamped to safe range)
__device__ __forceinline__ float fexp8(float x) {
  x = fmaxf(fminf(x, 60.0f), -60.0f);
  float y = x * 1.4426950408889634f;
  int   i = __float2int_rn(y);
  float f = y - (float)i;
  float p = 1.33335581e-3f;
  p = p*f + 9.61812911e-3f;
  p = p*f + 5.55041087e-2f;
  p = p*f + 2.40226507e-1f;
  p = p*f + 6.93147180e-1f;
  p = p*f + 1.0f;
  return p * __int_as_float((i + 119) << 23);
}

__device__ __forceinline__ uint32_t smem_u32(const void* p) {
  uint32_t a;
  asm("{ .reg .u64 t; cvta.to.shared.u64 t, %1; cvt.u32.u64 %0, t; }" : "=r"(a) : "l"(p));
  return a;
}
__device__ __forceinline__ void ldm_x4(uint32_t& r0, uint32_t& r1, uint32_t& r2,
                                       uint32_t& r3, uint32_t addr) {
  asm volatile("ldmatrix.sync.aligned.m8n8.x4.shared.b16 {%0,%1,%2,%3}, [%4];"
               : "=r"(r0), "=r"(r1), "=r"(r2), "=r"(r3) : "r"(addr));
}
__device__ __forceinline__ void mma16816(float* c, uint32_t a0, uint32_t a1,
                                         uint32_t a2, uint32_t a3,
                                         uint32_t b0, uint32_t b1) {
  asm volatile(
      "mma.sync.aligned.m16n8k16.row.col.f32.f16.f16.f32 "
      "{%0,%1,%2,%3}, {%4,%5,%6,%7}, {%8,%9}, {%0,%1,%2,%3};"
      : "+f"(c[0]), "+f"(c[1]), "+f"(c[2]), "+f"(c[3])
      : "r"(a0), "r"(a1), "r"(a2), "r"(a3), "r"(b0), "r"(b1));
}

__device__ __forceinline__ int wscan(int v, int lane) {
  #pragma unroll
  for (int off = 1; off < 32; off <<= 1) {
    int t = __shfl_up_sync(0xffffffffu, v, off);
    if (lane >= off) v += t;
  }
  return v;
}

// dual warp-scan of the 49 block sums into sOff[64] (call with full block)
__device__ __forceinline__ void scan_bsums(int* sOff) {
  int tid = threadIdx.x;
  if (tid < 32) {
    int lane = tid;
    int a0 = (lane      < NB1) ? g_bsum[lane]      : 0;
    int a1 = (32 + lane < NB1) ? g_bsum[32 + lane] : 0;
    int i0 = wscan(a0, lane);
    int t0 = __shfl_sync(0xffffffffu, i0, 31);
    int i1 = wscan(a1, lane) + t0;
    sOff[lane]      = i0 - a0;
    sOff[32 + lane] = i1 - a1;
  }
  __syncthreads();
}

// ---------------- fused front: node transform | msg_emb | hist+rank -----------
__global__ __launch_bounds__(256) void k_front(
    const float* __restrict__ x, const float* __restrict__ gw,
    const float* __restrict__ aw_s, const float* __restrict__ aw_d,
    const float* __restrict__ msg, const float* __restrict__ fw,
    const float* __restrict__ fb, const int* __restrict__ ei) {
  int bid = blockIdx.x;
  int tid = threadIdx.x;
  if (bid < NODE_BLKS) {
    __shared__ float sw[256];
    __shared__ float satt[128];
    __shared__ float sx[16];
    sw[tid] = gw[tid];
    if (tid < 64)       satt[tid] = aw_s[tid];
    else if (tid < 128) satt[tid] = aw_d[tid-64];
    int n0 = bid*4;
    if (tid < 16) sx[tid] = x[n0*4 + tid];
    __syncthreads();
    int local = tid >> 6, j = tid & 63;
    int node = n0 + local;
    float h = sx[local*4+0]*sw[j]     + sx[local*4+1]*sw[64+j]
            + sx[local*4+2]*sw[128+j] + sx[local*4+3]*sw[192+j];
    g_hb[node*64 + j] = __float2half(h);
    float ps = h*satt[j], pd = h*satt[64+j];
    #pragma unroll
    for (int off = 8; off > 0; off >>= 1) {
      ps += __shfl_xor_sync(0xffffffffu, ps, off);
      pd += __shfl_xor_sync(0xffffffffu, pd, off);
    }
    if ((j & 15) == 0) {
      int head = j >> 4;
      g_as4[node*4+head] = ps;
      g_ad4[node*4+head] = pd;
    }
  } else if (bid < NODE_BLKS + MSG_BLKS) {
    int b = (bid - NODE_BLKS)*4 + (tid >> 6);
    int j = tid & 63;
    const float* mr = msg + b*HIDDEN;
    float acc = fb[j];
    #pragma unroll 8
    for (int k = 0; k < HIDDEN; k++)
      acc += mr[k] * fw[k*64 + j];
    g_m[b*64 + j] = __float2half(acc);
  } else {
    // 2-replica histogram + rank capture; replica = (i>>2)&1 (reproducible)
    int i = (bid - NODE_BLKS - MSG_BLKS)*1024 + tid*4;
    if (i + 4 <= N_EDGES) {
      int rep = (i >> 2) & 1;
      int* cnt = g_cnt2 + rep*N_NODES;
      int4 d4 = *(const int4*)(ei + N_EDGES + i);
      ushort4 r4;
      r4.x = (uint16_t)atomicAdd(&cnt[d4.x], 1);
      r4.y = (uint16_t)atomicAdd(&cnt[d4.y], 1);
      r4.z = (uint16_t)atomicAdd(&cnt[d4.z], 1);
      r4.w = (uint16_t)atomicAdd(&cnt[d4.w], 1);
      *(ushort4*)(g_rank + i) = r4;
    } else {
      for (int e = i; e < N_EDGES; e++) {
        int rep = (e >> 2) & 1;
        g_rank[e] = (uint16_t)atomicAdd(&g_cnt2[rep*N_NODES + ei[N_EDGES + e]], 1);
      }
    }
  }
}

// ---------------- CSR scan over total counts (c0+c1); counters kept for scatter
__global__ void k_scan1() {
  __shared__ int wsum[32];
  int tid = threadIdx.x, lane = tid & 31, wid = tid >> 5;
  int i = blockIdx.x*1024 + tid;
  int v = 0;
  if (i < N_NODES) v = g_cnt2[i] + g_cnt2[N_NODES + i];
  int incl = wscan(v, lane);
  if (lane == 31) wsum[wid] = incl;
  __syncthreads();
  if (wid == 0) wsum[lane] = wscan(wsum[lane], lane);
  __syncthreads();
  int base = wid ? wsum[wid-1] : 0;
  if (i < N_NODES) g_off[i] = base + incl - v;
  if (tid == 1023) g_bsum[blockIdx.x] = wsum[31];
}

// atomic-free scatter: pos = off[d] + sOff[d>>10] + (rep ? c0[d] : 0) + rank
__global__ __launch_bounds__(256) void k_scatter(const int* __restrict__ ei) {
  __shared__ int sOff[64];
  scan_bsums(sOff);
  int i = (blockIdx.x*blockDim.x + threadIdx.x)*4;
  if (i + 4 <= N_EDGES) {
    int rep = (i >> 2) & 1;
    int4 s4 = *(const int4*)(ei + i);
    int4 d4 = *(const int4*)(ei + N_EDGES + i);
    ushort4 r4 = *(const ushort4*)(g_rank + i);
    int b0 = rep ? __ldg(&g_cnt2[d4.x]) : 0;
    int b1 = rep ? __ldg(&g_cnt2[d4.y]) : 0;
    int b2 = rep ? __ldg(&g_cnt2[d4.z]) : 0;
    int b3 = rep ? __ldg(&g_cnt2[d4.w]) : 0;
    int p0 = __ldg(&g_off[d4.x]) + sOff[d4.x >> 10] + b0 + r4.x;
    int p1 = __ldg(&g_off[d4.y]) + sOff[d4.y >> 10] + b1 + r4.y;
    int p2 = __ldg(&g_off[d4.z]) + sOff[d4.z >> 10] + b2 + r4.z;
    int p3 = __ldg(&g_off[d4.w]) + sOff[d4.w >> 10] + b3 + r4.w;
    g_esrc[p0] = s4.x;
    g_esrc[p1] = s4.y;
    g_esrc[p2] = s4.z;
    g_esrc[p3] = s4.w;
  } else {
    for (int e = i; e < N_EDGES; e++) {
      int rep = (e >> 2) & 1;
      int d = ei[N_EDGES + e];
      int pos = g_off[d] + sOff[d >> 10] + (rep ? g_cnt2[d] : 0) + g_rank[e];
      g_esrc[pos] = ei[e];
    }
  }
}

// ---------------- fused softmax + aggregation (one warp / node) ----------------
// 128-thread blocks (4 warps): higher occupancy ceiling and 2x less per-block
// degree-variance straggling than 256. HFMA2 inner loop, transposed smem caches.
__global__ __launch_bounds__(128) void k_agg(const float* __restrict__ gat_b) {
  __shared__ int sOff[64];
  __shared__ __align__(16) int     sS [4][32];      // src*32
  __shared__ __align__(16) __half2 sWT[4][4][32];   // [warp][head][edge] (w,w) fp16x2
  scan_bsums(sOff);
  int tid = threadIdx.x;
  int w = tid >> 5, lane = tid & 31;
  int n = (blockIdx.x*blockDim.x + tid) >> 5;   // grid sized exactly: n < N_NODES
  int beg = g_off[n] + sOff[n >> 10];
  int end = (n+1 < N_NODES) ? (__ldg(&g_off[n+1]) + sOff[(n+1) >> 10]) : N_EDGES;
  if (lane == 0) { g_cnt2[n] = 0; g_cnt2[N_NODES + n] = 0; }
  float4 ad = *(const float4*)&g_ad4[n*4];

  int h = lane >> 3;          // head of columns (2l, 2l+1)
  const __half2* hb2 = (const __half2*)g_hb;
  float acc0 = 0.f, acc1 = 0.f;
  float t0 = 0.f, t1 = 0.f, t2 = 0.f, t3 = 0.f;

  for (int base = beg; base < end; base += 32) {
    int e = base + lane;
    int src = 0;
    __half2 w0 = __float2half2_rn(0.f), w1 = w0, w2 = w0, w3 = w0;
    if (e < end) {
      src = __ldg(&g_esrc[e]);
      float4 as = *(const float4*)&g_as4[src*4];
      float e0 = fexp8(lrelu(as.x+ad.x));
      float e1 = fexp8(lrelu(as.y+ad.y));
      float e2 = fexp8(lrelu(as.z+ad.z));
      float e3 = fexp8(lrelu(as.w+ad.w));
      t0 += e0; t1 += e1; t2 += e2; t3 += e3;
      w0 = __float2half2_rn(e0);
      w1 = __float2half2_rn(e1);
      w2 = __float2half2_rn(e2);
      w3 = __float2half2_rn(e3);
    }
    sS[w][lane] = src*32;
    sWT[w][0][lane] = w0;
    sWT[w][1][lane] = w1;
    sWT[w][2][lane] = w2;
    sWT[w][3][lane] = w3;
    __syncwarp();
    int cnt = min(32, end - base);
    __half2 ah = __float2half2_rn(0.f);
    int j = 0;
    for (; j + 4 <= cnt; j += 4) {
      int4 ss = *(const int4*)&sS[w][j];
      uint2 wp0 = *(const uint2*)&sWT[w][h][j];       // 2 x half2
      uint2 wp1 = *(const uint2*)&sWT[w][h][j+2];
      __half2 v0 = __ldg(&hb2[ss.x + lane]);
      __half2 v1 = __ldg(&hb2[ss.y + lane]);
      __half2 v2 = __ldg(&hb2[ss.z + lane]);
      __half2 v3 = __ldg(&hb2[ss.w + lane]);
      ah = __hfma2(*reinterpret_cast<__half2*>(&wp0.x), v0, ah);
      ah = __hfma2(*reinterpret_cast<__half2*>(&wp0.y), v1, ah);
      ah = __hfma2(*reinterpret_cast<__half2*>(&wp1.x), v2, ah);
      ah = __hfma2(*reinterpret_cast<__half2*>(&wp1.y), v3, ah);
    }
    for (; j < cnt; j++) {
      ah = __hfma2(sWT[w][h][j], __ldg(&hb2[sS[w][j] + lane]), ah);
    }
    float2 af = __half22float2(ah);
    acc0 += af.x;
    acc1 += af.y;
    __syncwarp();
  }
  #pragma unroll
  for (int off = 16; off > 0; off >>= 1) {
    t0 += __shfl_xor_sync(0xffffffffu, t0, off);
    t1 += __shfl_xor_sync(0xffffffffu, t1, off);
    t2 += __shfl_xor_sync(0xffffffffu, t2, off);
    t3 += __shfl_xor_sync(0xffffffffu, t3, off);
  }
  float th = (h == 0) ? t0 : (h == 1) ? t1 : (h == 2) ? t2 : t3;
  float inv = 1.f/(th + 1e-16f);
  float2 gb = *(const float2*)&gat_b[2*lane];
  float v0 = acc0*inv + gb.x;
  float v1 = acc1*inv + gb.y;
  __half2 o2 = __floats2half2_rn(v0, v1);
  ((uint32_t*)g_hB)[n*32 + lane] = *reinterpret_cast<uint32_t*>(&o2);
}

// ---------------- shared GEMM mainloop: fp16 single-term, K=64 (4 ksteps) -----
#define A_LD     144
#define B_LD     144
#define B_OFF    (128*A_LD)                 // 18432
#define SMEM_DYN (128*A_LD + 128*B_LD)      // 36864
__device__ __forceinline__ void gemm_mainloop(char* smem, uint32_t sb,
                                              int bm, int bn, float acc[4][4][4]) {
  uint32_t sbA = sb;
  uint32_t sbB = sb + B_OFF;
  int tid = threadIdx.x, wid = tid >> 5, lid = tid & 31;

  const uint4* srcA = (const uint4*)g_m;
  const uint4* srcB = (const uint4*)g_hB;
  #pragma unroll
  for (int i = tid; i < 1024; i += 256) {   // A: 128 rows x 8 chunks
    int row = i >> 3, ch = i & 7;
    uint4 va = srcA[(size_t)(bm + row)*8 + ch];
    *(uint4*)(smem + row*A_LD + ch*16) = va;
  }
  #pragma unroll
  for (int i = tid; i < 1024; i += 256) {   // B: 128 rows x 8 chunks
    int row = i >> 3, ch = i & 7;
    int node = bn + row;
    uint4 vb = make_uint4(0u,0u,0u,0u);
    if (node < N_NODES) vb = srcB[(size_t)node*8 + ch];
    *(uint4*)(smem + B_OFF + row*B_LD + ch*16) = vb;
  }
  __syncthreads();

  int wm = wid & 1, wn = wid >> 1;
  #pragma unroll
  for (int i = 0; i < 4; i++)
    #pragma unroll
    for (int j = 0; j < 4; j++)
      #pragma unroll
      for (int c = 0; c < 4; c++) acc[i][j][c] = 0.f;

  #pragma unroll
  for (int ks = 0; ks < 4; ks++) {
    uint32_t a[4][4];
    #pragma unroll
    for (int mf = 0; mf < 4; mf++) {
      uint32_t addr = sbA + (wm*64 + mf*16 + (lid & 15))*A_LD
                          + ks*32 + (lid >> 4)*16;
      ldm_x4(a[mf][0], a[mf][1], a[mf][2], a[mf][3], addr);
    }
    uint32_t b[4][2];
    #pragma unroll
    for (int nfp = 0; nfp < 2; nfp++) {
      uint32_t addr = sbB + (wn*32 + nfp*16 + ((lid >> 4) & 1)*8 + (lid & 7))*B_LD
                          + ks*32 + ((lid >> 3) & 1)*16;
      uint32_t r0, r1, r2, r3;
      ldm_x4(r0, r1, r2, r3, addr);
      b[nfp*2][0] = r0;   b[nfp*2][1] = r1;
      b[nfp*2+1][0] = r2; b[nfp*2+1][1] = r3;
    }
    #pragma unroll
    for (int mf = 0; mf < 4; mf++)
      #pragma unroll
      for (int nf = 0; nf < 4; nf++)
        mma16816(acc[mf][nf], a[mf][0], a[mf][1], a[mf][2], a[mf][3],
                 b[nf][0], b[nf][1]);
  }
}

// ---------------- GEMM pass 1: per-row (max, sumexp) partials only ------------
__global__ __launch_bounds__(256, 2)
void k_gemm1() {
  extern __shared__ char smem[];
  uint32_t sb = smem_u32(smem);
  int tid = threadIdx.x, wid = tid >> 5, lid = tid & 31;
  int bm = blockIdx.x * 128;
  int bn = blockIdx.y * 128;
  bool fullTile = (bn + 128 <= N_NODES);

  float acc[4][4][4];
  gemm_mainloop(smem, sb, bm, bn, acc);
  __syncthreads();

  float* srm = (float*)smem;           // [128][4]
  float* srs = (float*)smem + 512;     // [128][4]
  int wm = wid & 1, wn = wid >> 1;

  #pragma unroll
  for (int mf = 0; mf < 4; mf++) {
    #pragma unroll
    for (int h = 0; h < 2; h++) {
      float v[8];
      #pragma unroll
      for (int nf = 0; nf < 4; nf++) {
        v[nf*2]   = acc[mf][nf][h*2];
        v[nf*2+1] = acc[mf][nf][h*2+1];
      }
      if (!fullTile) {
        #pragma unroll
        for (int nf = 0; nf < 4; nf++) {
          int colb = bn + wn*32 + nf*8 + (lid & 3)*2;
          if (colb   >= N_NODES) v[nf*2]   = -1e30f;
          if (colb+1 >= N_NODES) v[nf*2+1] = -1e30f;
        }
      }
      float m = v[0];
      #pragma unroll
      for (int t = 1; t < 8; t++) m = fmaxf(m, v[t]);
      m = fmaxf(m, __shfl_xor_sync(0xffffffffu, m, 1));
      m = fmaxf(m, __shfl_xor_sync(0xffffffffu, m, 2));
      float s = 0.f;
      #pragma unroll
      for (int t = 0; t < 8; t++) s += fexp(v[t] - m);
      s += __shfl_xor_sync(0xffffffffu, s, 1);
      s += __shfl_xor_sync(0xffffffffu, s, 2);
      if ((lid & 3) == 0) {
        int row = wm*64 + mf*16 + h*8 + (lid >> 2);
        srm[row*4 + wn] = m;
        srs[row*4 + wn] = s;
      }
    }
  }
  __syncthreads();
  if (tid < 128) {
    float m = srm[tid*4];
    m = fmaxf(m, srm[tid*4+1]);
    m = fmaxf(m, srm[tid*4+2]);
    m = fmaxf(m, srm[tid*4+3]);
    float s = 0.f;
    #pragma unroll
    for (int g = 0; g < 4; g++)
      s += srs[tid*4+g] * fexp(srm[tid*4+g] - m);
    g_pmax[(size_t)(bm+tid)*NTN + blockIdx.y] = m;
    g_psum[(size_t)(bm+tid)*NTN + blockIdx.y] = s;
  }
}

// ---------------- final lse from partials --------------------------------------
__global__ void k_lse() {   // grid 128, block 256 (8 warps) -> 1024 rows
  int wid = threadIdx.x >> 5, lid = threadIdx.x & 31;
  int row = blockIdx.x*8 + wid;
  float m = -1e30f, s = 0.f;
  for (int i = lid; i < NTN; i += 32) {
    float mi = g_pmax[(size_t)row*NTN + i];
    float si = g_psum[(size_t)row*NTN + i];
    float nm = fmaxf(m, mi);
    s = s*__expf(m - nm) + si*__expf(mi - nm);
    m = nm;
  }
  #pragma unroll
  for (int off = 16; off > 0; off >>= 1) {
    float om = __shfl_xor_sync(0xffffffffu, m, off);
    float os = __shfl_xor_sync(0xffffffffu, s, off);
    float nm = fmaxf(m, om);
    s = s*__expf(m - nm) + os*__expf(om - nm);
    m = nm;
  }
  if (lid == 0) g_lse[row] = m + logf(s);
}

// ---------------- GEMM pass 2: recompute, subtract lse, direct STG.64 ---------
__global__ __launch_bounds__(256, 2)
void k_gemm2(float* __restrict__ out) {
  extern __shared__ char smem[];
  uint32_t sb = smem_u32(smem);
  int tid = threadIdx.x, wid = tid >> 5, lid = tid & 31;
  int bm = blockIdx.x * 128;
  int bn = blockIdx.y * 128;

  float acc[4][4][4];
  gemm_mainloop(smem, sb, bm, bn, acc);
  __syncthreads();

  float* slse = (float*)smem;
  if (tid < 128) slse[tid] = g_lse[bm + tid];
  __syncthreads();

  int wm = wid & 1, wn = wid >> 1;
  int rsub = (lid >> 2);
  int cbase = bn + wn*32 + (lid & 3)*2;
  #pragma unroll
  for (int mf = 0; mf < 4; mf++) {
    int r1 = wm*64 + mf*16 + rsub;
    float l1 = slse[r1];
    float l2 = slse[r1 + 8];
    float* orow1 = out + (size_t)(bm + r1    )*N_NODES;
    float* orow2 = out + (size_t)(bm + r1 + 8)*N_NODES;
    #pragma unroll
    for (int nf = 0; nf < 4; nf++) {
      int col = cbase + nf*8;
      if (col < N_NODES) {   // N even, col even -> pair fully valid
        *(float2*)(orow1 + col) = make_float2(acc[mf][nf][0] - l1, acc[mf][nf][1] - l1);
        *(float2*)(orow2 + col) = make_float2(acc[mf][nf][2] - l2, acc[mf][nf][3] - l2);
      }
    }
  }
}

// ---------------- launch --------------------------------------------------------
extern "C" void kernel_launch(void* const* d_in, const int* in_sizes, int n_in,
                              void* d_out, int out_size) {
  const float* message = (const float*)d_in[0];
  const float* x       = (const float*)d_in[1];
  const int*   eidx    = (const int*)  d_in[2];
  const float* gat_w   = (const float*)d_in[3];
  const float* att_src = (const float*)d_in[4];
  const float* att_dst = (const float*)d_in[5];
  const float* gat_b   = (const float*)d_in[6];
  const float* fc_w    = (const float*)d_in[7];
  const float* fc_b    = (const float*)d_in[8];
  float* out = (float*)d_out;

  cudaFuncSetAttribute(k_gemm1, cudaFuncAttributeMaxDynamicSharedMemorySize, SMEM_DYN);
  cudaFuncSetAttribute(k_gemm2, cudaFuncAttributeMaxDynamicSharedMemorySize, SMEM_DYN);

  k_front  <<<NODE_BLKS + MSG_BLKS + HIST_BLKS, 256>>>(
      x, gat_w, att_src, att_dst, message, fc_w, fc_b, eidx);
  k_scan1  <<<NB1, 1024>>>();
  k_scatter<<<HIST_BLKS, 256>>>(eidx);
  k_agg    <<<(N_NODES*32)/128, 128>>>(gat_b);
  k_gemm1  <<<dim3(BATCH/128, NTN), 256, SMEM_DYN>>>();
  k_lse    <<<BATCH/8, 256>>>();
  k_gemm2  <<<dim3(BATCH/128, NTN), 256, SMEM_DYN>>>(out);
}